// round 1
// baseline (speedup 1.0000x reference)
#include <cuda_runtime.h>

// MultiLayerDeepSNN: 15-step LIF SNN, B=16384.
// Layers: in6 -> 256 -> 256 -> 256 -> 256 -> 128 -> 3 (output averaged over steps)
// Strategy (round 1 baseline): fp32 scalar pipeline, one kernel per stage,
// all state in __device__ scratch arrays, ~92 launches per graph invocation.

#define NB 16384
#define THRV 1.0f

// ---------------- scratch (static __device__, allowed by harness rules) ----
__device__ float g_cur1[NB * 256];
__device__ float g_mem1[NB * 256];
__device__ float g_mem2[NB * 256];
__device__ float g_mem3[NB * 256];
__device__ float g_mem4[NB * 256];
__device__ float g_mem5[NB * 128];
__device__ float g_spkA[NB * 256];
__device__ float g_spkB[NB * 256];

// ---------------- init: zero membranes + output accumulator ----------------
__global__ void k_zero(float* __restrict__ out, int out_n) {
    int idx = blockIdx.x * blockDim.x + threadIdx.x;
    int stride = gridDim.x * blockDim.x;
    for (int i = idx; i < NB * 256; i += stride) {
        g_mem1[i] = 0.f; g_mem2[i] = 0.f; g_mem3[i] = 0.f; g_mem4[i] = 0.f;
    }
    for (int i = idx; i < NB * 128; i += stride) g_mem5[i] = 0.f;
    for (int i = idx; i < out_n; i += stride) out[i] = 0.f;
}

// ---------------- cur1 = x @ W1^T + b1 (K=6), computed once ----------------
__global__ void k_cur1(const float* __restrict__ x, const float* __restrict__ W1,
                       const float* __restrict__ b1) {
    int idx = blockIdx.x * blockDim.x + threadIdx.x;   // over NB*256
    int b = idx >> 8;
    int o = idx & 255;
    const float* xr = x + b * 6;
    const float* wr = W1 + o * 6;
    float s = __ldg(b1 + o);
#pragma unroll
    for (int i = 0; i < 6; i++) s = fmaf(__ldg(xr + i), __ldg(wr + i), s);
    g_cur1[idx] = s;
}

// ---------------- LIF layer 1 (elementwise, cur1 constant) -----------------
__global__ void k_lif1() {
    int idx = blockIdx.x * blockDim.x + threadIdx.x;   // over NB*256/4
    float4 m = reinterpret_cast<float4*>(g_mem1)[idx];
    float4 c = reinterpret_cast<float4*>(g_cur1)[idx];
    float4 nm, s;
    nm.x = 0.90f * m.x + c.x - (m.x > THRV ? THRV : 0.f); s.x = nm.x > THRV ? 1.f : 0.f;
    nm.y = 0.90f * m.y + c.y - (m.y > THRV ? THRV : 0.f); s.y = nm.y > THRV ? 1.f : 0.f;
    nm.z = 0.90f * m.z + c.z - (m.z > THRV ? THRV : 0.f); s.z = nm.z > THRV ? 1.f : 0.f;
    nm.w = 0.90f * m.w + c.w - (m.w > THRV ? THRV : 0.f); s.w = nm.w > THRV ? 1.f : 0.f;
    reinterpret_cast<float4*>(g_mem1)[idx] = nm;
    reinterpret_cast<float4*>(g_spkA)[idx] = s;
}

// ---------------- fused GEMM (spk_in @ W^T + b) + LIF update ---------------
// A: [NB,256] spikes (row major), W: [N,256] row major, mem/spk: [NB,N].
// CTA tile 128x128, K-tile 16, per-thread 8x8 micro-tile.
__global__ __launch_bounds__(256, 2) void k_gemm_lif(
    const float* __restrict__ A, const float* __restrict__ W,
    const float* __restrict__ bias, float* __restrict__ mem,
    float* __restrict__ spk, int N, float beta) {
    __shared__ float As[16 * 132];
    __shared__ float Bs[16 * 132];

    const int tid = threadIdx.x;
    const int m0 = blockIdx.x * 128;
    const int n0 = blockIdx.y * 128;
    const float* Ap = A + (size_t)m0 * 256;
    const float* Wp = W + (size_t)n0 * 256;

    const int r0 = tid >> 2;            // 0..63
    const int c0 = (tid & 3) * 4;       // 0,4,8,12 (floats within K-tile)

    // prefetch K-tile 0
    float4 pa0 = *(const float4*)(Ap + r0 * 256 + c0);
    float4 pa1 = *(const float4*)(Ap + (r0 + 64) * 256 + c0);
    float4 pb0 = *(const float4*)(Wp + r0 * 256 + c0);
    float4 pb1 = *(const float4*)(Wp + (r0 + 64) * 256 + c0);

    const int tx = tid & 15;            // n micro-tile
    const int ty = tid >> 4;            // m micro-tile
    float acc[8][8];
#pragma unroll
    for (int i = 0; i < 8; i++)
#pragma unroll
        for (int j = 0; j < 8; j++) acc[i][j] = 0.f;

#pragma unroll 1
    for (int kt = 0; kt < 16; ++kt) {
        // stage to smem (layout [k][m], padded stride 132)
        As[(c0 + 0) * 132 + r0] = pa0.x;
        As[(c0 + 1) * 132 + r0] = pa0.y;
        As[(c0 + 2) * 132 + r0] = pa0.z;
        As[(c0 + 3) * 132 + r0] = pa0.w;
        As[(c0 + 0) * 132 + r0 + 64] = pa1.x;
        As[(c0 + 1) * 132 + r0 + 64] = pa1.y;
        As[(c0 + 2) * 132 + r0 + 64] = pa1.z;
        As[(c0 + 3) * 132 + r0 + 64] = pa1.w;
        Bs[(c0 + 0) * 132 + r0] = pb0.x;
        Bs[(c0 + 1) * 132 + r0] = pb0.y;
        Bs[(c0 + 2) * 132 + r0] = pb0.z;
        Bs[(c0 + 3) * 132 + r0] = pb0.w;
        Bs[(c0 + 0) * 132 + r0 + 64] = pb1.x;
        Bs[(c0 + 1) * 132 + r0 + 64] = pb1.y;
        Bs[(c0 + 2) * 132 + r0 + 64] = pb1.z;
        Bs[(c0 + 3) * 132 + r0 + 64] = pb1.w;
        __syncthreads();

        if (kt < 15) {  // prefetch next K-tile while computing this one
            int k0 = (kt + 1) * 16;
            pa0 = *(const float4*)(Ap + r0 * 256 + k0 + c0);
            pa1 = *(const float4*)(Ap + (r0 + 64) * 256 + k0 + c0);
            pb0 = *(const float4*)(Wp + r0 * 256 + k0 + c0);
            pb1 = *(const float4*)(Wp + (r0 + 64) * 256 + k0 + c0);
        }

#pragma unroll
        for (int k = 0; k < 16; k++) {
            float4 a0 = *(float4*)&As[k * 132 + ty * 8];
            float4 a1 = *(float4*)&As[k * 132 + ty * 8 + 4];
            float4 b0 = *(float4*)&Bs[k * 132 + tx * 8];
            float4 b1 = *(float4*)&Bs[k * 132 + tx * 8 + 4];
            float av[8] = {a0.x, a0.y, a0.z, a0.w, a1.x, a1.y, a1.z, a1.w};
            float bv[8] = {b0.x, b0.y, b0.z, b0.w, b1.x, b1.y, b1.z, b1.w};
#pragma unroll
            for (int i = 0; i < 8; i++)
#pragma unroll
                for (int j = 0; j < 8; j++)
                    acc[i][j] = fmaf(av[i], bv[j], acc[i][j]);
        }
        __syncthreads();
    }

    // epilogue: c = acc + bias; LIF: reset from PREVIOUS mem (subtract mech.)
    float4 bb0 = *(const float4*)(bias + n0 + tx * 8);
    float4 bb1 = *(const float4*)(bias + n0 + tx * 8 + 4);
    float bArr[8] = {bb0.x, bb0.y, bb0.z, bb0.w, bb1.x, bb1.y, bb1.z, bb1.w};

#pragma unroll
    for (int i = 0; i < 8; i++) {
        size_t gi = (size_t)(m0 + ty * 8 + i) * N + n0 + tx * 8;
        float4 m0v = *(float4*)(mem + gi);
        float4 m1v = *(float4*)(mem + gi + 4);
        float mp[8] = {m0v.x, m0v.y, m0v.z, m0v.w, m1v.x, m1v.y, m1v.z, m1v.w};
        float nmv[8], sv[8];
#pragma unroll
        for (int j = 0; j < 8; j++) {
            float cv = acc[i][j] + bArr[j];
            float r = mp[j] > THRV ? THRV : 0.f;
            nmv[j] = beta * mp[j] + cv - r;
            sv[j] = nmv[j] > THRV ? 1.f : 0.f;
        }
        *(float4*)(mem + gi)     = make_float4(nmv[0], nmv[1], nmv[2], nmv[3]);
        *(float4*)(mem + gi + 4) = make_float4(nmv[4], nmv[5], nmv[6], nmv[7]);
        *(float4*)(spk + gi)     = make_float4(sv[0], sv[1], sv[2], sv[3]);
        *(float4*)(spk + gi + 4) = make_float4(sv[4], sv[5], sv[6], sv[7]);
    }
}

// ---------------- output stage: out += spk5 @ W6^T + b6 (N=3, K=128) -------
__global__ void k_out(const float* __restrict__ spk5, const float* __restrict__ W6,
                      const float* __restrict__ b6, float* __restrict__ out,
                      int finalize) {
    __shared__ float w[384];
    for (int i = threadIdx.x; i < 384; i += blockDim.x) w[i] = W6[i];
    __syncthreads();
    int b = blockIdx.x * blockDim.x + threadIdx.x;   // over NB
    const float* s = spk5 + (size_t)b * 128;
    float s0 = __ldg(b6 + 0), s1 = __ldg(b6 + 1), s2 = __ldg(b6 + 2);
#pragma unroll 8
    for (int k = 0; k < 128; k++) {
        float v = s[k];
        s0 = fmaf(v, w[k], s0);
        s1 = fmaf(v, w[128 + k], s1);
        s2 = fmaf(v, w[256 + k], s2);
    }
    float o0 = out[b * 3 + 0] + s0;
    float o1 = out[b * 3 + 1] + s1;
    float o2 = out[b * 3 + 2] + s2;
    if (finalize) {
        const float inv = 1.f / 15.f;
        o0 *= inv; o1 *= inv; o2 *= inv;
    }
    out[b * 3 + 0] = o0;
    out[b * 3 + 1] = o1;
    out[b * 3 + 2] = o2;
}

// ---------------- launch --------------------------------------------------
extern "C" void kernel_launch(void* const* d_in, const int* in_sizes, int n_in,
                              void* d_out, int out_size) {
    const float* x  = (const float*)d_in[0];
    const float* W1 = (const float*)d_in[1];
    const float* b1 = (const float*)d_in[2];
    const float* W2 = (const float*)d_in[3];
    const float* b2 = (const float*)d_in[4];
    const float* W3 = (const float*)d_in[5];
    const float* b3 = (const float*)d_in[6];
    const float* W4 = (const float*)d_in[7];
    const float* b4 = (const float*)d_in[8];
    const float* W5 = (const float*)d_in[9];
    const float* b5 = (const float*)d_in[10];
    const float* W6 = (const float*)d_in[11];
    const float* b6 = (const float*)d_in[12];
    float* out = (float*)d_out;

    // resolve scratch symbol addresses (host side, no allocation)
    float *p_spkA, *p_spkB, *p_mem2, *p_mem3, *p_mem4, *p_mem5;
    cudaGetSymbolAddress((void**)&p_spkA, g_spkA);
    cudaGetSymbolAddress((void**)&p_spkB, g_spkB);
    cudaGetSymbolAddress((void**)&p_mem2, g_mem2);
    cudaGetSymbolAddress((void**)&p_mem3, g_mem3);
    cudaGetSymbolAddress((void**)&p_mem4, g_mem4);
    cudaGetSymbolAddress((void**)&p_mem5, g_mem5);

    k_zero<<<2048, 256>>>(out, out_size);
    k_cur1<<<NB, 256>>>(x, W1, b1);

    dim3 g256(NB / 128, 2);   // N=256 stages
    dim3 g128(NB / 128, 1);   // N=128 stage

    for (int t = 0; t < 15; ++t) {
        k_lif1<<<NB * 256 / 4 / 256, 256>>>();
        k_gemm_lif<<<g256, 256>>>(p_spkA, W2, b2, p_mem2, p_spkB, 256, 0.88f);
        k_gemm_lif<<<g256, 256>>>(p_spkB, W3, b3, p_mem3, p_spkA, 256, 0.86f);
        k_gemm_lif<<<g256, 256>>>(p_spkA, W4, b4, p_mem4, p_spkB, 256, 0.84f);
        k_gemm_lif<<<g128, 256>>>(p_spkB, W5, b5, p_mem5, p_spkA, 128, 0.82f);
        k_out<<<NB / 256, 256>>>(p_spkA, W6, b6, out, t == 14 ? 1 : 0);
    }
}

// round 3
// speedup vs baseline: 2.0617x; 2.0617x over previous
#include <cuda_runtime.h>
#include <cuda_fp16.h>
#include <cstdint>

// MultiLayerDeepSNN: 15-step LIF SNN, B=16384, layers 6->256->256->256->256->128->3.
// Round 3: fp16 hi/lo tensor-core GEMM (mma.sync m16n8k16, fp32 accum) fused with LIF.
// Exactness: spikes are {0,1} (exact fp16); weights split w = hi+lo (fp16 each),
// residual ~2^-22 relative -> same accuracy class as fp32 GEMM.

#define NB 16384
#define THRV 1.0f

// ---------------- scratch -------------------------------------------------
__device__ float g_cur1[NB * 256];
__device__ float g_mem1[NB * 256];
__device__ float g_mem2[NB * 256];
__device__ float g_mem3[NB * 256];
__device__ float g_mem4[NB * 256];
__device__ float g_mem5[NB * 128];
__device__ __half g_spkA[NB * 256];
__device__ __half g_spkB[NB * 256];
// weight hi/lo: W2@0, W3@65536, W4@131072, W5@196608 (128x256)
__device__ __half g_Wh[3 * 65536 + 32768];
__device__ __half g_Wl[3 * 65536 + 32768];

// ---------------- helpers -------------------------------------------------
__device__ __forceinline__ unsigned int s2u(const void* p) {
    return (unsigned int)__cvta_generic_to_shared(p);
}
__device__ __forceinline__ void cp16(void* dst, const void* src) {
    asm volatile("cp.async.cg.shared.global [%0], [%1], 16;"
                 :: "r"(s2u(dst)), "l"(src));
}
__device__ __forceinline__ void ldmx4(unsigned int& r0, unsigned int& r1,
                                      unsigned int& r2, unsigned int& r3,
                                      unsigned int addr) {
    asm volatile("ldmatrix.sync.aligned.m8n8.x4.shared.b16 {%0,%1,%2,%3}, [%4];"
                 : "=r"(r0), "=r"(r1), "=r"(r2), "=r"(r3) : "r"(addr));
}
__device__ __forceinline__ void mma16816(float* c, const unsigned int* a,
                                         const unsigned int* b) {
    asm volatile(
        "mma.sync.aligned.m16n8k16.row.col.f32.f16.f16.f32 "
        "{%0,%1,%2,%3},{%4,%5,%6,%7},{%8,%9},{%0,%1,%2,%3};"
        : "+f"(c[0]), "+f"(c[1]), "+f"(c[2]), "+f"(c[3])
        : "r"(a[0]), "r"(a[1]), "r"(a[2]), "r"(a[3]), "r"(b[0]), "r"(b[1]));
}

// ---------------- init ----------------------------------------------------
__global__ void k_zero(float* __restrict__ out, int out_n) {
    int idx = blockIdx.x * blockDim.x + threadIdx.x;
    int stride = gridDim.x * blockDim.x;
    for (int i = idx; i < NB * 256; i += stride) {
        g_mem1[i] = 0.f; g_mem2[i] = 0.f; g_mem3[i] = 0.f; g_mem4[i] = 0.f;
    }
    for (int i = idx; i < NB * 128; i += stride) g_mem5[i] = 0.f;
    for (int i = idx; i < out_n; i += stride) out[i] = 0.f;
}

// ---------------- weight split: w -> hi (fp16) + lo (fp16) ----------------
__global__ void k_split(const float* __restrict__ W, __half* __restrict__ hi,
                        __half* __restrict__ lo, int n) {
    int i = blockIdx.x * blockDim.x + threadIdx.x;
    if (i < n) {
        float w = W[i];
        __half h = __float2half_rn(w);
        hi[i] = h;
        lo[i] = __float2half_rn(w - __half2float(h));
    }
}

// ---------------- cur1 = x @ W1^T + b1 (K=6), once -------------------------
__global__ void k_cur1(const float* __restrict__ x, const float* __restrict__ W1,
                       const float* __restrict__ b1) {
    int idx = blockIdx.x * blockDim.x + threadIdx.x;
    int b = idx >> 8, o = idx & 255;
    const float* xr = x + b * 6;
    const float* wr = W1 + o * 6;
    float s = __ldg(b1 + o);
#pragma unroll
    for (int i = 0; i < 6; i++) s = fmaf(__ldg(xr + i), __ldg(wr + i), s);
    g_cur1[idx] = s;
}

// ---------------- LIF layer 1 (elementwise) -> fp16 spikes -----------------
__global__ void k_lif1() {
    int idx = blockIdx.x * blockDim.x + threadIdx.x;  // over NB*256/4
    float4 m = reinterpret_cast<float4*>(g_mem1)[idx];
    float4 c = reinterpret_cast<float4*>(g_cur1)[idx];
    float4 nm;
    nm.x = 0.90f * m.x + c.x - (m.x > THRV ? THRV : 0.f);
    nm.y = 0.90f * m.y + c.y - (m.y > THRV ? THRV : 0.f);
    nm.z = 0.90f * m.z + c.z - (m.z > THRV ? THRV : 0.f);
    nm.w = 0.90f * m.w + c.w - (m.w > THRV ? THRV : 0.f);
    reinterpret_cast<float4*>(g_mem1)[idx] = nm;
    __half2 h0 = __floats2half2_rn(nm.x > THRV ? 1.f : 0.f, nm.y > THRV ? 1.f : 0.f);
    __half2 h1 = __floats2half2_rn(nm.z > THRV ? 1.f : 0.f, nm.w > THRV ? 1.f : 0.f);
    uint2 pk;
    pk.x = *(unsigned int*)&h0;
    pk.y = *(unsigned int*)&h1;
    reinterpret_cast<uint2*>(g_spkA)[idx] = pk;
}

// ---------------- fused tensor-core GEMM + LIF -----------------------------
// C = spk[M,256] @ W^T + b, W given as hi/lo fp16 [N,256] row-major (= col-major B).
// CTA tile 128x128, BK=32, 8 warps (2x4), warp tile 64x32. cp.async double buffer.
#define TILE_H (128 * 40)   // halfs per staged matrix (40-half padded rows)
__global__ __launch_bounds__(256, 2) void k_gemm_lif_mma(
    const __half* __restrict__ A, const __half* __restrict__ Wh,
    const __half* __restrict__ Wl, const float* __restrict__ bias,
    float* __restrict__ mem, __half* __restrict__ spk, int N, float beta) {
    extern __shared__ __half smbuf[];  // [2][3][TILE_H]

    const int tid = threadIdx.x;
    const int lane = tid & 31, wid = tid >> 5;
    const int wm = wid >> 2, wn = wid & 3;
    const int m0 = blockIdx.x * 128, n0 = blockIdx.y * 128;

    // global->smem: thread covers row tid>>1, 16 halfs at offset (tid&1)*16
    const int ldr = tid >> 1;
    const int ldo = (tid & 1) * 16;
    const __half* Ag = A + (size_t)(m0 + ldr) * 256 + ldo;
    const __half* Hg = Wh + (size_t)(n0 + ldr) * 256 + ldo;
    const __half* Lg = Wl + (size_t)(n0 + ldr) * 256 + ldo;
    const int soff = ldr * 40 + ldo;

    float acc[4][4][4];
#pragma unroll
    for (int i = 0; i < 4; i++)
#pragma unroll
        for (int j = 0; j < 4; j++)
#pragma unroll
            for (int q = 0; q < 4; q++) acc[i][j][q] = 0.f;

    // ldmatrix lane geometry
    const int aRowL = (lane & 15);
    const int aColL = (lane >> 4) * 8;
    const int bRowL = (lane & 7) + ((lane >> 4) & 1) * 8;
    const int bColL = ((lane >> 3) & 1) * 8;

#pragma unroll 1
    for (int kc = 0; kc < 8; ++kc) {
        int buf = kc & 1;
        if (kc == 0) {
            __half* d = smbuf;
            cp16(d + soff, Ag); cp16(d + soff + 8, Ag + 8);
            cp16(d + TILE_H + soff, Hg); cp16(d + TILE_H + soff + 8, Hg + 8);
            cp16(d + 2 * TILE_H + soff, Lg); cp16(d + 2 * TILE_H + soff + 8, Lg + 8);
            asm volatile("cp.async.commit_group;");
        }
        if (kc < 7) {
            const __half* a = Ag + (kc + 1) * 32;
            const __half* h = Hg + (kc + 1) * 32;
            const __half* l = Lg + (kc + 1) * 32;
            __half* d = smbuf + (buf ^ 1) * 3 * TILE_H;
            cp16(d + soff, a); cp16(d + soff + 8, a + 8);
            cp16(d + TILE_H + soff, h); cp16(d + TILE_H + soff + 8, h + 8);
            cp16(d + 2 * TILE_H + soff, l); cp16(d + 2 * TILE_H + soff + 8, l + 8);
            asm volatile("cp.async.commit_group;");
            asm volatile("cp.async.wait_group 1;");
        } else {
            asm volatile("cp.async.wait_group 0;");
        }
        __syncthreads();

        const __half* sA = smbuf + buf * 3 * TILE_H;
        const __half* sH = sA + TILE_H;
        const __half* sL = sH + TILE_H;

#pragma unroll
        for (int kk = 0; kk < 2; ++kk) {
            unsigned int aF[4][4];
#pragma unroll
            for (int mt = 0; mt < 4; mt++) {
                unsigned int ad = s2u(sA + (wm * 64 + mt * 16 + aRowL) * 40 + kk * 16 + aColL);
                ldmx4(aF[mt][0], aF[mt][1], aF[mt][2], aF[mt][3], ad);
            }
            unsigned int hF[4][2], lF[4][2];
#pragma unroll
            for (int p = 0; p < 2; p++) {
                unsigned int r0, r1, r2, r3;
                unsigned int bd = s2u(sH + (wn * 32 + p * 16 + bRowL) * 40 + kk * 16 + bColL);
                ldmx4(r0, r1, r2, r3, bd);
                hF[2 * p][0] = r0; hF[2 * p][1] = r1;
                hF[2 * p + 1][0] = r2; hF[2 * p + 1][1] = r3;
                unsigned int ld = s2u(sL + (wn * 32 + p * 16 + bRowL) * 40 + kk * 16 + bColL);
                ldmx4(r0, r1, r2, r3, ld);
                lF[2 * p][0] = r0; lF[2 * p][1] = r1;
                lF[2 * p + 1][0] = r2; lF[2 * p + 1][1] = r3;
            }
#pragma unroll
            for (int mt = 0; mt < 4; mt++)
#pragma unroll
                for (int nt = 0; nt < 4; nt++) {
                    mma16816(acc[mt][nt], aF[mt], hF[nt]);
                    mma16816(acc[mt][nt], aF[mt], lF[nt]);
                }
        }
        __syncthreads();
    }

    // ---------------- epilogue: bias + LIF (reset from PREVIOUS mem) -------
    const int rowBase = m0 + wm * 64 + (lane >> 2);
    const int colBase = n0 + wn * 32 + (lane & 3) * 2;
#pragma unroll
    for (int mt = 0; mt < 4; mt++) {
        int r = rowBase + mt * 16;
#pragma unroll
        for (int nt = 0; nt < 4; nt++) {
            int c = colBase + nt * 8;
            size_t gi0 = (size_t)r * N + c;
            size_t gi1 = (size_t)(r + 8) * N + c;
            float2 bb = *(const float2*)(bias + c);
            float2 mp0 = *(float2*)(mem + gi0);
            float2 mp1 = *(float2*)(mem + gi1);
            float cv0 = acc[mt][nt][0] + bb.x;
            float cv1 = acc[mt][nt][1] + bb.y;
            float cv2 = acc[mt][nt][2] + bb.x;
            float cv3 = acc[mt][nt][3] + bb.y;
            float n0v = beta * mp0.x + cv0 - (mp0.x > THRV ? THRV : 0.f);
            float n1v = beta * mp0.y + cv1 - (mp0.y > THRV ? THRV : 0.f);
            float n2v = beta * mp1.x + cv2 - (mp1.x > THRV ? THRV : 0.f);
            float n3v = beta * mp1.y + cv3 - (mp1.y > THRV ? THRV : 0.f);
            *(float2*)(mem + gi0) = make_float2(n0v, n1v);
            *(float2*)(mem + gi1) = make_float2(n2v, n3v);
            __half2 s0 = __floats2half2_rn(n0v > THRV ? 1.f : 0.f, n1v > THRV ? 1.f : 0.f);
            __half2 s1 = __floats2half2_rn(n2v > THRV ? 1.f : 0.f, n3v > THRV ? 1.f : 0.f);
            *(__half2*)(spk + gi0) = s0;
            *(__half2*)(spk + gi1) = s1;
        }
    }
}

// ---------------- output stage: out += spk5 @ W6^T + b6 (N=3, K=128) -------
__global__ void k_out(const __half* __restrict__ spk5, const float* __restrict__ W6,
                      const float* __restrict__ b6, float* __restrict__ out,
                      int finalize) {
    __shared__ float w[384];
    for (int i = threadIdx.x; i < 384; i += blockDim.x) w[i] = W6[i];
    __syncthreads();
    int b = blockIdx.x * blockDim.x + threadIdx.x;
    const __half2* sp = (const __half2*)(spk5 + (size_t)b * 128);
    float s0 = __ldg(b6 + 0), s1 = __ldg(b6 + 1), s2v = __ldg(b6 + 2);
#pragma unroll 8
    for (int k = 0; k < 64; k++) {
        float2 v = __half22float2(sp[k]);
        s0 = fmaf(v.x, w[2 * k], s0);
        s0 = fmaf(v.y, w[2 * k + 1], s0);
        s1 = fmaf(v.x, w[128 + 2 * k], s1);
        s1 = fmaf(v.y, w[128 + 2 * k + 1], s1);
        s2v = fmaf(v.x, w[256 + 2 * k], s2v);
        s2v = fmaf(v.y, w[256 + 2 * k + 1], s2v);
    }
    float o0 = out[b * 3 + 0] + s0;
    float o1 = out[b * 3 + 1] + s1;
    float o2 = out[b * 3 + 2] + s2v;
    if (finalize) {
        const float inv = 1.f / 15.f;
        o0 *= inv; o1 *= inv; o2 *= inv;
    }
    out[b * 3 + 0] = o0;
    out[b * 3 + 1] = o1;
    out[b * 3 + 2] = o2;
}

// ---------------- launch --------------------------------------------------
extern "C" void kernel_launch(void* const* d_in, const int* in_sizes, int n_in,
                              void* d_out, int out_size) {
    const float* x  = (const float*)d_in[0];
    const float* W1 = (const float*)d_in[1];
    const float* b1 = (const float*)d_in[2];
    const float* W2 = (const float*)d_in[3];
    const float* b2 = (const float*)d_in[4];
    const float* W3 = (const float*)d_in[5];
    const float* b3 = (const float*)d_in[6];
    const float* W4 = (const float*)d_in[7];
    const float* b4 = (const float*)d_in[8];
    const float* W5 = (const float*)d_in[9];
    const float* b5 = (const float*)d_in[10];
    const float* W6 = (const float*)d_in[11];
    const float* b6 = (const float*)d_in[12];
    float* out = (float*)d_out;

    __half *p_spkA, *p_spkB, *p_Wh, *p_Wl;
    float *p_mem2, *p_mem3, *p_mem4, *p_mem5;
    cudaGetSymbolAddress((void**)&p_spkA, g_spkA);
    cudaGetSymbolAddress((void**)&p_spkB, g_spkB);
    cudaGetSymbolAddress((void**)&p_Wh, g_Wh);
    cudaGetSymbolAddress((void**)&p_Wl, g_Wl);
    cudaGetSymbolAddress((void**)&p_mem2, g_mem2);
    cudaGetSymbolAddress((void**)&p_mem3, g_mem3);
    cudaGetSymbolAddress((void**)&p_mem4, g_mem4);
    cudaGetSymbolAddress((void**)&p_mem5, g_mem5);

    const int SMEM = 2 * 3 * TILE_H * (int)sizeof(__half);  // 61440
    cudaFuncSetAttribute(k_gemm_lif_mma, cudaFuncAttributeMaxDynamicSharedMemorySize, SMEM);

    k_zero<<<2048, 256>>>(out, out_size);
    k_cur1<<<NB, 256>>>(x, W1, b1);
    k_split<<<(65536 + 255) / 256, 256>>>(W2, p_Wh, p_Wl, 65536);
    k_split<<<(65536 + 255) / 256, 256>>>(W3, p_Wh + 65536, p_Wl + 65536, 65536);
    k_split<<<(65536 + 255) / 256, 256>>>(W4, p_Wh + 131072, p_Wl + 131072, 65536);
    k_split<<<(32768 + 255) / 256, 256>>>(W5, p_Wh + 196608, p_Wl + 196608, 32768);

    dim3 g256(NB / 128, 2);
    dim3 g128(NB / 128, 1);

    for (int t = 0; t < 15; ++t) {
        k_lif1<<<NB * 256 / 4 / 256, 256>>>();
        k_gemm_lif_mma<<<g256, 256, SMEM>>>(p_spkA, p_Wh, p_Wl, b2, p_mem2, p_spkB, 256, 0.88f);
        k_gemm_lif_mma<<<g256, 256, SMEM>>>(p_spkB, p_Wh + 65536, p_Wl + 65536, b3, p_mem3, p_spkA, 256, 0.86f);
        k_gemm_lif_mma<<<g256, 256, SMEM>>>(p_spkA, p_Wh + 131072, p_Wl + 131072, b4, p_mem4, p_spkB, 256, 0.84f);
        k_gemm_lif_mma<<<g128, 256, SMEM>>>(p_spkB, p_Wh + 196608, p_Wl + 196608, b5, p_mem5, p_spkA, 128, 0.82f);
        k_out<<<NB / 256, 256>>>(p_spkA, W6, b6, out, t == 14 ? 1 : 0);
    }
}